// round 6
// baseline (speedup 1.0000x reference)
#include <cuda_runtime.h>
#include <math_constants.h>

#define B_ROWS 8192
#define VOCAB  32000
#define KNEG   5
#define SDOM   100
#define EPSV   1e-10f

// Persistent grid: 152 SMs x 8 resident blocks (256 thr, 32 regs) = one wave.
#define GRID   1216

// Self-resetting accumulator state: zero at load; the LAST finishing block
// reads it, writes the output, and resets it, so every graph replay sees
// identical initial state.
__device__ double       g_acc   = 0.0;
__device__ unsigned int g_count = 0;

__global__ __launch_bounds__(256)
void bo4_persist_kernel(const float* __restrict__ yHat,
                        const float* __restrict__ prob,
                        const int*   __restrict__ y,
                        const int*   __restrict__ ind,
                        float*       __restrict__ out)
{
    __shared__ float smax[2][8];          // double buffer: 1 sync per row
    const int tid  = threadIdx.x;
    const int wid  = tid >> 5;
    const int lane = tid & 31;

    double acc = 0.0;                     // thread 0's running loss sum
    int it = 0;

    for (int b = blockIdx.x; b < B_ROWS; b += GRID, ++it) {
        const float*  row  = yHat + (size_t)b * VOCAB;
        const float4* row4 = reinterpret_cast<const float4*>(row);

        // ---- row max over 8000 float4, streaming (evict-first) ----
        float m = -CUDART_INF_F;
        #pragma unroll 4
        for (int i = tid; i < VOCAB / 4; i += 256) {
            float4 v = __ldcs(row4 + i);
            m = fmaxf(m, fmaxf(fmaxf(v.x, v.y), fmaxf(v.z, v.w)));
        }
        #pragma unroll
        for (int o = 16; o > 0; o >>= 1)
            m = fmaxf(m, __shfl_xor_sync(0xFFFFFFFFu, m, o));

        const int p = it & 1;
        if (lane == 0) smax[p][wid] = m;
        __syncthreads();   // non-leader warps immediately start next row's loads

        // ---- per-row tail on thread 0 only ----
        if (tid == 0) {
            float mm = smax[p][0];
            #pragma unroll
            for (int w = 1; w < 8; w++) mm = fmaxf(mm, smax[p][w]);

            const int yy = __ldg(y + b);
            const float Yg_l = __ldg(row + yy) - mm;
            const float* prow = prob + (size_t)yy * SDOM;

            float pk[KNEG], comp[KNEG];
            float q = CUDART_INF_F;
            #pragma unroll
            for (int k = 0; k < KNEG; k++) {
                const int idx = __ldg(ind + b * KNEG + k);   // idx in [0,100)
                comp[k] = __ldg(row + idx) - mm;
                pk[k]   = 1.0f / __ldg(prow + idx);
                q       = fminf(q, pk[k]);
            }

            float Yg  = q * __expf(Yg_l);
            float sum = Yg;
            float c[KNEG];
            #pragma unroll
            for (int k = 0; k < KNEG; k++) {
                c[k] = pk[k] * __expf(comp[k]);
                sum += c[k];
            }
            const float inv = 1.0f / sum;

            float term = __logf(Yg * inv + EPSV);
            #pragma unroll
            for (int k = 0; k < KNEG; k++)
                term += __logf(1.0f - c[k] * inv + EPSV);

            acc += (double)term;
        }
    }

    // ---- one atomic per block, last-block finalize + state reset ----
    if (tid == 0) {
        atomicAdd(&g_acc, acc);
        __threadfence();
        unsigned int t = atomicAdd(&g_count, 1u);
        if (t == (unsigned)(GRID - 1)) {
            out[0] = (float)(-g_acc / (double)(B_ROWS * (KNEG + 1)));
            g_acc   = 0.0;       // restore initial state for next replay
            g_count = 0u;
            __threadfence();
        }
    }
}

extern "C" void kernel_launch(void* const* d_in, const int* in_sizes, int n_in,
                              void* d_out, int out_size)
{
    const float* yHat = (const float*)d_in[0];   // [B, V] fp32
    const float* prob = (const float*)d_in[1];   // [V, S] fp32
    const int*   y    = (const int*)  d_in[2];   // [B]    int32
    const int*   ind  = (const int*)  d_in[3];   // [B, K] int32

    bo4_persist_kernel<<<GRID, 256>>>(yHat, prob, y, ind, (float*)d_out);
}

// round 8
// speedup vs baseline: 1.0947x; 1.0947x over previous
#include <cuda_runtime.h>
#include <math_constants.h>

#define B_ROWS 8192
#define VOCAB  32000
#define KNEG   5
#define SDOM   100
#define EPSV   1e-10f

// Self-resetting accumulator state for graph-replay determinism.
__device__ double       g_acc   = 0.0;
__device__ unsigned int g_count = 0;

__global__ __launch_bounds__(256, 8)   // force 8 CTAs/SM (<=32 regs)
void bo4_fused_kernel(const float* __restrict__ yHat,
                      const float* __restrict__ prob,
                      const int*   __restrict__ y,
                      const int*   __restrict__ ind,
                      float*       __restrict__ out)
{
    const int b    = blockIdx.x;
    const int tid  = threadIdx.x;
    const int wid  = tid >> 5;
    const int lane = tid & 31;

    const float*  row  = yHat + (size_t)b * VOCAB;
    const float4* row4 = reinterpret_cast<const float4*>(row);

    // ---- PREFETCH tail operands (warp 0) so their DRAM/L2 latency ----
    // ---- overlaps the row scan instead of trailing it.             ----
    float pre_yg = 0.f, pre_c = 0.f, pre_p = 1.f;
    if (wid == 0) {
        const int yy = __ldg(y + b);            // uniform across warp
        pre_yg = __ldg(row + yy);
        if (lane < KNEG) {
            const int idx = __ldg(ind + b * KNEG + lane);   // idx in [0,100)
            pre_c = __ldg(row + idx);
            pre_p = __ldg(prob + (size_t)yy * SDOM + idx);
        }
    }

    // ---- row max over 32000 floats (8000 float4), streaming ----
    float m = -CUDART_INF_F;
    #pragma unroll 4
    for (int i = tid; i < VOCAB / 4; i += 256) {
        float4 v = __ldcs(row4 + i);            // evict-first: one-pass stream
        m = fmaxf(m, fmaxf(fmaxf(v.x, v.y), fmaxf(v.z, v.w)));
    }
    #pragma unroll
    for (int o = 16; o > 0; o >>= 1)
        m = fmaxf(m, __shfl_xor_sync(0xFFFFFFFFu, m, o));

    __shared__ float smax[8];
    if (lane == 0) smax[wid] = m;
    __syncthreads();

    // ---- warp-cooperative tail: pure ALU, operands already in regs ----
    if (wid == 0) {
        float mm = smax[0];
        #pragma unroll
        for (int w = 1; w < 8; w++) mm = fmaxf(mm, smax[w]);

        const float pinv = 1.0f / pre_p;                        // lanes>=K: 1.0
        // q = min_k p_k
        float qv = (lane < KNEG) ? pinv : CUDART_INF_F;
        #pragma unroll
        for (int o = 16; o > 0; o >>= 1)
            qv = fminf(qv, __shfl_xor_sync(0xFFFFFFFFu, qv, o));

        // per-lane complement term c_k = p_k * exp(comp_k)
        const float ck = (lane < KNEG) ? pinv * __expf(pre_c - mm) : 0.f;
        float sc = ck;
        #pragma unroll
        for (int o = 16; o > 0; o >>= 1)
            sc += __shfl_xor_sync(0xFFFFFFFFu, sc, o);

        const float Yg  = qv * __expf(pre_yg - mm);             // pre_yg valid lane-uniform? lane0's copy
        // pre_yg is identical across all lanes of warp 0 (uniform load), OK.
        const float inv = 1.0f / (Yg + sc);

        // per-lane log(1 - c_k/sum + eps), reduced; lane 0 adds target term
        float lt = (lane < KNEG) ? __logf(1.0f - ck * inv + EPSV) : 0.f;
        #pragma unroll
        for (int o = 16; o > 0; o >>= 1)
            lt += __shfl_xor_sync(0xFFFFFFFFu, lt, o);

        if (lane == 0) {
            const float term = __logf(Yg * inv + EPSV) + lt;
            atomicAdd(&g_acc, (double)term);
            __threadfence();
            unsigned int t = atomicAdd(&g_count, 1u);
            if (t == (unsigned)(B_ROWS - 1)) {
                out[0] = (float)(-g_acc / (double)(B_ROWS * (KNEG + 1)));
                g_acc   = 0.0;      // restore state for next graph replay
                g_count = 0u;
                __threadfence();
            }
        }
    }
}

extern "C" void kernel_launch(void* const* d_in, const int* in_sizes, int n_in,
                              void* d_out, int out_size)
{
    const float* yHat = (const float*)d_in[0];   // [B, V] fp32
    const float* prob = (const float*)d_in[1];   // [V, S] fp32
    const int*   y    = (const int*)  d_in[2];   // [B]    int32
    const int*   ind  = (const int*)  d_in[3];   // [B, K] int32

    bo4_fused_kernel<<<B_ROWS, 256>>>(yHat, prob, y, ind, (float*)d_out);
}